// round 1
// baseline (speedup 1.0000x reference)
#include <cuda_runtime.h>
#include <cstdint>

// Problem constants (fixed shapes for NTXent_678604833492)
#define BATCH 4096
#define NROWS 8192          // 2*BATCH
#define DIMK  128
#define SA    129           // padded smem row stride (floats)

// Scratch (allocation-free rule: __device__ globals)
__device__ float g_zn[NROWS * DIMK];        // normalized rows      (4 MB)
__device__ float g_part[64 * NROWS];        // per-coltile row sums (2 MB)
__device__ float g_rowloss[NROWS];          // per-row loss         (32 KB)

// ---------------------------------------------------------------------------
// packed f32x2 helpers (FFMA2 path: 2x FFMA throughput on sm_103a)
// ---------------------------------------------------------------------------
__device__ __forceinline__ unsigned long long pack2(float lo, float hi) {
    unsigned long long r;
    asm("mov.b64 %0, {%1, %2};" : "=l"(r) : "f"(lo), "f"(hi));
    return r;
}
__device__ __forceinline__ unsigned long long fma2(unsigned long long a,
                                                   unsigned long long b,
                                                   unsigned long long c) {
    unsigned long long d;
    asm("fma.rn.f32x2 %0, %1, %2, %3;" : "=l"(d) : "l"(a), "l"(b), "l"(c));
    return d;
}
__device__ __forceinline__ void unpack2(unsigned long long v, float& lo, float& hi) {
    asm("mov.b64 {%0, %1}, %2;" : "=f"(lo), "=f"(hi) : "l"(v));
}
__device__ __forceinline__ float ex2_approx(float x) {
    float r;
    asm("ex2.approx.ftz.f32 %0, %1;" : "=f"(r) : "f"(x));
    return r;
}
__device__ __forceinline__ float lg2_approx(float x) {
    float r;
    asm("lg2.approx.f32 %0, %1;" : "=f"(r) : "f"(x));
    return r;
}

// ---------------------------------------------------------------------------
// Kernel 1: L2-normalize rows of [zx; zy] -> g_zn.  One warp per row.
// ---------------------------------------------------------------------------
__global__ __launch_bounds__(256)
void k_normalize(const float* __restrict__ zx, const float* __restrict__ zy) {
    int warp = threadIdx.x >> 5;
    int lane = threadIdx.x & 31;
    int row  = blockIdx.x * 8 + warp;
    if (row >= NROWS) return;

    const float* src = (row < BATCH) ? (zx + (size_t)row * DIMK)
                                     : (zy + (size_t)(row - BATCH) * DIMK);
    float4 v = reinterpret_cast<const float4*>(src)[lane];
    float ss = v.x * v.x + v.y * v.y + v.z * v.z + v.w * v.w;
    #pragma unroll
    for (int off = 16; off > 0; off >>= 1)
        ss += __shfl_xor_sync(0xffffffffu, ss, off);
    float inv = 1.0f / fmaxf(sqrtf(ss), 1e-8f);
    float4 o;
    o.x = v.x * inv; o.y = v.y * inv; o.z = v.z * inv; o.w = v.w * inv;
    reinterpret_cast<float4*>(g_zn + (size_t)row * DIMK)[lane] = o;
}

// ---------------------------------------------------------------------------
// Kernel 2: 128x128x128 GEMM tile + fused exp row-sum epilogue.
//   block (bi, bj): rows bi*128.., cols bj*128..
//   sumexp partial over this col tile -> g_part[bj][row]
//   Diagonal (j == i) excluded exactly.
// ---------------------------------------------------------------------------
__global__ __launch_bounds__(256, 1)
void k_simtile() {
    extern __shared__ float sm[];
    float* sA = sm;                 // [128][SA]
    float* sB = sm + 128 * SA;      // [128][SA]

    const int tid = threadIdx.x;
    const int bi  = blockIdx.y;     // row tile
    const int bj  = blockIdx.x;     // col tile
    const int rowA0 = bi * 128;
    const int rowB0 = bj * 128;

    // cooperative load: 128 rows x 32 float4 per tile, 256 threads
    #pragma unroll
    for (int i = tid; i < 128 * 32; i += 256) {
        int r  = i >> 5;
        int kc = (i & 31) << 2;
        float4 va = *reinterpret_cast<const float4*>(g_zn + (size_t)(rowA0 + r) * DIMK + kc);
        float* pa = sA + r * SA + kc;
        pa[0] = va.x; pa[1] = va.y; pa[2] = va.z; pa[3] = va.w;
        float4 vb = *reinterpret_cast<const float4*>(g_zn + (size_t)(rowB0 + r) * DIMK + kc);
        float* pb = sB + r * SA + kc;
        pb[0] = vb.x; pb[1] = vb.y; pb[2] = vb.z; pb[3] = vb.w;
    }
    __syncthreads();

    const int tx = tid & 15;        // col group
    const int ty = tid >> 4;        // row group
    const int ra = ty * 8;          // 8 rows: ra..ra+7
    const int cb = tx * 4;          // cols: cb..cb+3 and cb+64..cb+67

    unsigned long long acc[8][4];
    #pragma unroll
    for (int r = 0; r < 8; r++)
        #pragma unroll
        for (int p = 0; p < 4; p++) acc[r][p] = 0ULL;

    #pragma unroll 8
    for (int k = 0; k < DIMK; k++) {
        float b0 = sB[(cb + 0) * SA + k];
        float b1 = sB[(cb + 1) * SA + k];
        float b2 = sB[(cb + 2) * SA + k];
        float b3 = sB[(cb + 3) * SA + k];
        float b4 = sB[(cb + 64) * SA + k];
        float b5 = sB[(cb + 65) * SA + k];
        float b6 = sB[(cb + 66) * SA + k];
        float b7 = sB[(cb + 67) * SA + k];
        unsigned long long bp0 = pack2(b0, b1);
        unsigned long long bp1 = pack2(b2, b3);
        unsigned long long bp2 = pack2(b4, b5);
        unsigned long long bp3 = pack2(b6, b7);
        #pragma unroll
        for (int r = 0; r < 8; r++) {
            float a = sA[(ra + r) * SA + k];
            unsigned long long ap = pack2(a, a);
            acc[r][0] = fma2(ap, bp0, acc[r][0]);
            acc[r][1] = fma2(ap, bp1, acc[r][1]);
            acc[r][2] = fma2(ap, bp2, acc[r][2]);
            acc[r][3] = fma2(ap, bp3, acc[r][3]);
        }
    }

    // epilogue: exp((cos-1)*2) = exp2((cos-1)*2*log2e), exclude diagonal
    const float CEXP = 2.8853900817779268f;  // 2 * log2(e)
    float rsum[8];
    #pragma unroll
    for (int r = 0; r < 8; r++) {
        int grow = rowA0 + ra + r;
        float s = 0.0f;
        #pragma unroll
        for (int p = 0; p < 4; p++) {
            float s0, s1;
            unpack2(acc[r][p], s0, s1);
            int gcol0 = rowB0 + cb + ((p < 2) ? 2 * p : 64 + 2 * (p - 2));
            float e0 = ex2_approx((s0 - 1.0f) * CEXP);
            float e1 = ex2_approx((s1 - 1.0f) * CEXP);
            if (grow == gcol0)     e0 = 0.0f;
            if (grow == gcol0 + 1) e1 = 0.0f;
            s += e0 + e1;
        }
        rsum[r] = s;
    }

    // reduce over the 16 tx threads (same half-warp group) per row
    #pragma unroll
    for (int r = 0; r < 8; r++) {
        float v = rsum[r];
        #pragma unroll
        for (int off = 8; off > 0; off >>= 1)
            v += __shfl_xor_sync(0xffffffffu, v, off, 16);
        rsum[r] = v;
    }
    if (tx == 0) {
        #pragma unroll
        for (int r = 0; r < 8; r++)
            g_part[(size_t)bj * NROWS + rowA0 + ra + r] = rsum[r];
    }
}

// ---------------------------------------------------------------------------
// Kernel 3: per-row loss = 2 + ln(sumexp_i) - 2*cos(i, pos(i)).  Warp per row.
// ---------------------------------------------------------------------------
__global__ __launch_bounds__(256)
void k_rowloss() {
    int warp = threadIdx.x >> 5;
    int lane = threadIdx.x & 31;
    int row  = blockIdx.x * 8 + warp;
    if (row >= NROWS) return;

    int p = (row < BATCH) ? row + BATCH : row - BATCH;
    float4 a = reinterpret_cast<const float4*>(g_zn + (size_t)row * DIMK)[lane];
    float4 b = reinterpret_cast<const float4*>(g_zn + (size_t)p * DIMK)[lane];
    float dot = a.x * b.x + a.y * b.y + a.z * b.z + a.w * b.w;
    #pragma unroll
    for (int off = 16; off > 0; off >>= 1)
        dot += __shfl_xor_sync(0xffffffffu, dot, off);

    float se = g_part[(size_t)lane * NROWS + row] +
               g_part[(size_t)(lane + 32) * NROWS + row];
    #pragma unroll
    for (int off = 16; off > 0; off >>= 1)
        se += __shfl_xor_sync(0xffffffffu, se, off);

    if (lane == 0) {
        float lnse = lg2_approx(se) * 0.6931471805599453f;
        g_rowloss[row] = 2.0f + lnse - 2.0f * dot;
    }
}

// ---------------------------------------------------------------------------
// Kernel 4: deterministic final reduction -> out[0] = sum / N
// ---------------------------------------------------------------------------
__global__ __launch_bounds__(256)
void k_finalreduce(float* __restrict__ out) {
    __shared__ float s[256];
    int tid = threadIdx.x;
    float acc = 0.0f;
    for (int i = tid; i < NROWS; i += 256) acc += g_rowloss[i];
    s[tid] = acc;
    __syncthreads();
    #pragma unroll
    for (int off = 128; off > 0; off >>= 1) {
        if (tid < off) s[tid] += s[tid + off];
        __syncthreads();
    }
    if (tid == 0) out[0] = s[0] / (float)NROWS;
}

// ---------------------------------------------------------------------------
extern "C" void kernel_launch(void* const* d_in, const int* in_sizes, int n_in,
                              void* d_out, int out_size) {
    const float* zx = (const float*)d_in[0];
    const float* zy = (const float*)d_in[1];
    float* out = (float*)d_out;

    const int smem = 2 * 128 * SA * sizeof(float);  // 132096 B
    cudaFuncSetAttribute(k_simtile, cudaFuncAttributeMaxDynamicSharedMemorySize, smem);

    k_normalize<<<NROWS / 8, 256>>>(zx, zy);
    dim3 grid(NROWS / 128, NROWS / 128);            // (bj, bi)
    k_simtile<<<grid, 256, smem>>>();
    k_rowloss<<<NROWS / 8, 256>>>();
    k_finalreduce<<<1, 256>>>(out);
}

// round 3
// speedup vs baseline: 7.9065x; 7.9065x over previous
#include <cuda_runtime.h>
#include <cuda_bf16.h>
#include <cstdint>

// Problem constants (fixed shapes for NTXent_678604833492)
#define BATCH 4096
#define NROWS 8192          // 2*BATCH
#define DIMK  128
#define NTILE 64            // NROWS / 128

// Scratch (__device__ globals; allocation-free rule)
__device__ float g_zn[NROWS * DIMK];                 // normalized fp32 (4 MB)
__device__ __nv_bfloat16 g_zbf[NROWS * DIMK];        // normalized bf16, row-major (2 MB)
__device__ float g_part[NTILE * NROWS];              // per-coltile row sumexp (2 MB)
__device__ float g_rowloss[NROWS];

// ---------------------------------------------------------------------------
// helpers
// ---------------------------------------------------------------------------
__device__ __forceinline__ float ex2_approx(float x) {
    float r; asm("ex2.approx.ftz.f32 %0, %1;" : "=f"(r) : "f"(x)); return r;
}
__device__ __forceinline__ float lg2_approx(float x) {
    float r; asm("lg2.approx.f32 %0, %1;" : "=f"(r) : "f"(x)); return r;
}
__device__ __forceinline__ uint32_t smem_u32(const void* p) {
    uint32_t a;
    asm("{ .reg .u64 t; cvta.to.shared.u64 t, %1; cvt.u32.u64 %0, t; }" : "=r"(a) : "l"(p));
    return a;
}
__device__ __forceinline__ void ldsm_x4(uint32_t addr, uint32_t* r) {
    asm volatile("ldmatrix.sync.aligned.m8n8.x4.shared.b16 {%0,%1,%2,%3}, [%4];"
                 : "=r"(r[0]), "=r"(r[1]), "=r"(r[2]), "=r"(r[3]) : "r"(addr));
}
__device__ __forceinline__ void mma16816(float* d, const uint32_t* a, uint32_t b0, uint32_t b1) {
    asm volatile(
        "mma.sync.aligned.m16n8k16.row.col.f32.bf16.bf16.f32 "
        "{%0,%1,%2,%3}, {%4,%5,%6,%7}, {%8,%9}, {%0,%1,%2,%3};"
        : "+f"(d[0]), "+f"(d[1]), "+f"(d[2]), "+f"(d[3])
        : "r"(a[0]), "r"(a[1]), "r"(a[2]), "r"(a[3]), "r"(b0), "r"(b1));
}

// smem tile addressing: row-major 128 rows x 256B, 16B chunk XOR-swizzled by row&7
__device__ __forceinline__ uint32_t swz(int row, int kchunk /*16B units*/) {
    return ((uint32_t)row << 8) + (uint32_t)((kchunk ^ (row & 7)) << 4);
}

// ---------------------------------------------------------------------------
// Kernel 1: normalize rows -> g_zn (fp32) and g_zbf (bf16 row-major)
// ---------------------------------------------------------------------------
__global__ __launch_bounds__(256)
void k_normalize(const float* __restrict__ zx, const float* __restrict__ zy) {
    int warp = threadIdx.x >> 5;
    int lane = threadIdx.x & 31;
    int row  = blockIdx.x * 8 + warp;
    if (row >= NROWS) return;

    const float* src = (row < BATCH) ? (zx + (size_t)row * DIMK)
                                     : (zy + (size_t)(row - BATCH) * DIMK);
    float4 v = reinterpret_cast<const float4*>(src)[lane];
    float ss = v.x * v.x + v.y * v.y + v.z * v.z + v.w * v.w;
    #pragma unroll
    for (int off = 16; off > 0; off >>= 1)
        ss += __shfl_xor_sync(0xffffffffu, ss, off);
    float inv = 1.0f / fmaxf(sqrtf(ss), 1e-8f);
    float4 o; o.x = v.x * inv; o.y = v.y * inv; o.z = v.z * inv; o.w = v.w * inv;
    reinterpret_cast<float4*>(g_zn + (size_t)row * DIMK)[lane] = o;

    __nv_bfloat162 p0 = __float22bfloat162_rn(make_float2(o.x, o.y));
    __nv_bfloat162 p1 = __float22bfloat162_rn(make_float2(o.z, o.w));
    uint32_t* dst = reinterpret_cast<uint32_t*>(g_zbf + (size_t)row * DIMK);
    dst[lane * 2]     = *reinterpret_cast<uint32_t*>(&p0);
    dst[lane * 2 + 1] = *reinterpret_cast<uint32_t*>(&p1);
}

// ---------------------------------------------------------------------------
// Kernel 2: 128x128x128 bf16 mma.sync tile + fused exp row-sum epilogue
//   smem: sA 32KB | sB 32KB | ssum 1KB
// ---------------------------------------------------------------------------
#define SMEM_SSUM 65536
#define SMEM_TOT  (65536 + 1024)

__global__ __launch_bounds__(256, 2)
void k_mma_tile() {
    extern __shared__ char smem[];
    const uint32_t sa = smem_u32(smem);
    const uint32_t sb = sa + 32768;
    float* ssum = reinterpret_cast<float*>(smem + SMEM_SSUM);

    const int tid  = threadIdx.x;
    const int wid  = tid >> 5;
    const int lane = tid & 31;
    const int bi = blockIdx.y;     // row tile
    const int bj = blockIdx.x;     // col tile

    // cooperative tile load: row-major gmem -> swizzled smem (16B per thread x 8)
    const uint4* gA = reinterpret_cast<const uint4*>(g_zbf + (size_t)bi * 128 * DIMK);
    const uint4* gB = reinterpret_cast<const uint4*>(g_zbf + (size_t)bj * 128 * DIMK);
    #pragma unroll
    for (int i = 0; i < 8; i++) {
        int idx = tid + i * 256;            // 0..2047
        int row = idx >> 4, c = idx & 15;
        uint32_t off = swz(row, c);
        *reinterpret_cast<uint4*>(smem + off)         = gA[idx];
        *reinterpret_cast<uint4*>(smem + 32768 + off) = gB[idx];
    }
    __syncthreads();

    // warp layout: 4 (M) x 2 (N); warp tile 32 x 64
    const int arow0 = (wid & 3) * 32;
    const int bcol0 = (wid >> 2) * 64;
    const int g  = lane >> 3;      // ldmatrix group 0..3
    const int rr = lane & 7;

    float acc[2][8][4];
    #pragma unroll
    for (int mt = 0; mt < 2; mt++)
        #pragma unroll
        for (int nt = 0; nt < 8; nt++)
            #pragma unroll
            for (int q = 0; q < 4; q++) acc[mt][nt][q] = 0.0f;

    #pragma unroll
    for (int ks = 0; ks < 8; ks++) {
        const int kc = ks * 2;     // 16B-chunk base of this k-step (16 bf16)
        uint32_t afr[2][4], bfr[4][4];
        #pragma unroll
        for (int mt = 0; mt < 2; mt++) {
            // matrices: m0 rows0-7/k0, m1 rows8-15/k0, m2 rows0-7/k8, m3 rows8-15/k8
            uint32_t addr = sa + swz(arow0 + mt * 16 + rr + (g & 1) * 8, kc + (g >> 1));
            ldsm_x4(addr, afr[mt]);
        }
        #pragma unroll
        for (int nq = 0; nq < 4; nq++) {
            // matrices: m0 n0-7/k0, m1 n0-7/k8, m2 n8-15/k0, m3 n8-15/k8
            uint32_t addr = sb + swz(bcol0 + nq * 16 + (g >> 1) * 8 + rr, kc + (g & 1));
            ldsm_x4(addr, bfr[nq]);
        }
        #pragma unroll
        for (int mt = 0; mt < 2; mt++)
            #pragma unroll
            for (int nt = 0; nt < 8; nt++)
                mma16816(acc[mt][nt], afr[mt], bfr[nt >> 1][(nt & 1) * 2],
                         bfr[nt >> 1][(nt & 1) * 2 + 1]);
    }

    // epilogue: exp2((cos-1)*2*log2e), mask diagonal, per-row sums
    const float CEXP = 2.8853900817779268f;   // 2 * log2(e)
    #pragma unroll
    for (int mt = 0; mt < 2; mt++) {
        #pragma unroll
        for (int rh = 0; rh < 2; rh++) {
            int lrow = arow0 + mt * 16 + (lane >> 2) + rh * 8;
            int grow = bi * 128 + lrow;
            float rs = 0.0f;
            #pragma unroll
            for (int nt = 0; nt < 8; nt++) {
                #pragma unroll
                for (int c = 0; c < 2; c++) {
                    float s = acc[mt][nt][rh * 2 + c];
                    int gcol = bj * 128 + bcol0 + nt * 8 + (lane & 3) * 2 + c;
                    float e = ex2_approx((s - 1.0f) * CEXP);
                    if (grow == gcol) e = 0.0f;
                    rs += e;
                }
            }
            rs += __shfl_xor_sync(0xffffffffu, rs, 1);
            rs += __shfl_xor_sync(0xffffffffu, rs, 2);
            if ((lane & 3) == 0) ssum[(wid >> 2) * 128 + lrow] = rs;
        }
    }
    __syncthreads();
    if (tid < 128)
        g_part[(size_t)bj * NROWS + bi * 128 + tid] = ssum[tid] + ssum[128 + tid];
}

// ---------------------------------------------------------------------------
// Kernel 3: per-row loss = 2 + ln(sumexp) - 2*cos(i, pos(i)).  Warp per row.
// ---------------------------------------------------------------------------
__global__ __launch_bounds__(256)
void k_rowloss() {
    int warp = threadIdx.x >> 5;
    int lane = threadIdx.x & 31;
    int row  = blockIdx.x * 8 + warp;
    if (row >= NROWS) return;

    int p = (row < BATCH) ? row + BATCH : row - BATCH;
    float4 a = reinterpret_cast<const float4*>(g_zn + (size_t)row * DIMK)[lane];
    float4 b = reinterpret_cast<const float4*>(g_zn + (size_t)p * DIMK)[lane];
    float dot = a.x * b.x + a.y * b.y + a.z * b.z + a.w * b.w;
    #pragma unroll
    for (int off = 16; off > 0; off >>= 1)
        dot += __shfl_xor_sync(0xffffffffu, dot, off);

    float se = g_part[(size_t)lane * NROWS + row] +
               g_part[(size_t)(lane + 32) * NROWS + row];
    #pragma unroll
    for (int off = 16; off > 0; off >>= 1)
        se += __shfl_xor_sync(0xffffffffu, se, off);

    if (lane == 0) {
        float lnse = lg2_approx(se) * 0.6931471805599453f;
        g_rowloss[row] = 2.0f + lnse - 2.0f * dot;
    }
}

// ---------------------------------------------------------------------------
// Kernel 4: deterministic final reduction -> out[0] = sum / N
// ---------------------------------------------------------------------------
__global__ __launch_bounds__(256)
void k_finalreduce(float* __restrict__ out) {
    __shared__ float s[256];
    int tid = threadIdx.x;
    float acc = 0.0f;
    for (int i = tid; i < NROWS; i += 256) acc += g_rowloss[i];
    s[tid] = acc;
    __syncthreads();
    #pragma unroll
    for (int off = 128; off > 0; off >>= 1) {
        if (tid < off) s[tid] += s[tid + off];
        __syncthreads();
    }
    if (tid == 0) out[0] = s[0] / (float)NROWS;
}

// ---------------------------------------------------------------------------
extern "C" void kernel_launch(void* const* d_in, const int* in_sizes, int n_in,
                              void* d_out, int out_size) {
    const float* zx = (const float*)d_in[0];
    const float* zy = (const float*)d_in[1];
    float* out = (float*)d_out;

    cudaFuncSetAttribute(k_mma_tile, cudaFuncAttributeMaxDynamicSharedMemorySize, SMEM_TOT);

    k_normalize<<<NROWS / 8, 256>>>(zx, zy);
    dim3 grid(NTILE, NTILE);            // (bj, bi)
    k_mma_tile<<<grid, 256, SMEM_TOT>>>();
    k_rowloss<<<NROWS / 8, 256>>>();
    k_finalreduce<<<1, 256>>>(out);
}

// round 4
// speedup vs baseline: 7.9105x; 1.0005x over previous
#include <cuda_runtime.h>
#include <cuda_bf16.h>
#include <cstdint>

// Problem constants (fixed shapes for NTXent_678604833492)
#define BATCH 4096
#define NROWS 8192          // 2*BATCH
#define DIMK  128
#define NTILE 64            // NROWS / 128

// Scratch (__device__ globals; allocation-free rule)
__device__ float g_zn[NROWS * DIMK];                 // normalized fp32 (4 MB)
__device__ __nv_bfloat16 g_zbf[NROWS * DIMK];        // normalized bf16, row-major (2 MB)
__device__ float g_part[NTILE * NROWS];              // per-coltile row sumexp (2 MB)
__device__ float g_rowloss[NROWS];

// ---------------------------------------------------------------------------
// helpers
// ---------------------------------------------------------------------------
__device__ __forceinline__ float ex2_approx(float x) {
    float r; asm("ex2.approx.ftz.f32 %0, %1;" : "=f"(r) : "f"(x)); return r;
}
__device__ __forceinline__ float lg2_approx(float x) {
    float r; asm("lg2.approx.f32 %0, %1;" : "=f"(r) : "f"(x)); return r;
}
__device__ __forceinline__ uint32_t smem_u32(const void* p) {
    uint32_t a;
    asm("{ .reg .u64 t; cvta.to.shared.u64 t, %1; cvt.u32.u64 %0, t; }" : "=r"(a) : "l"(p));
    return a;
}
__device__ __forceinline__ void ldsm_x4(uint32_t addr, uint32_t* r) {
    asm volatile("ldmatrix.sync.aligned.m8n8.x4.shared.b16 {%0,%1,%2,%3}, [%4];"
                 : "=r"(r[0]), "=r"(r[1]), "=r"(r[2]), "=r"(r[3]) : "r"(addr));
}
__device__ __forceinline__ void mma16816(float* d, const uint32_t* a, uint32_t b0, uint32_t b1) {
    asm volatile(
        "mma.sync.aligned.m16n8k16.row.col.f32.bf16.bf16.f32 "
        "{%0,%1,%2,%3}, {%4,%5,%6,%7}, {%8,%9}, {%0,%1,%2,%3};"
        : "+f"(d[0]), "+f"(d[1]), "+f"(d[2]), "+f"(d[3])
        : "r"(a[0]), "r"(a[1]), "r"(a[2]), "r"(a[3]), "r"(b0), "r"(b1));
}

// smem tile addressing: row-major 128 rows x 256B, 16B chunk XOR-swizzled by row&7
__device__ __forceinline__ uint32_t swz(int row, int kchunk /*16B units*/) {
    return ((uint32_t)row << 8) + (uint32_t)((kchunk ^ (row & 7)) << 4);
}

// ---------------------------------------------------------------------------
// Kernel 1: normalize rows -> g_zn (fp32) and g_zbf (bf16 row-major)
// ---------------------------------------------------------------------------
__global__ __launch_bounds__(256)
void k_normalize(const float* __restrict__ zx, const float* __restrict__ zy) {
    int warp = threadIdx.x >> 5;
    int lane = threadIdx.x & 31;
    int row  = blockIdx.x * 8 + warp;
    if (row >= NROWS) return;

    const float* src = (row < BATCH) ? (zx + (size_t)row * DIMK)
                                     : (zy + (size_t)(row - BATCH) * DIMK);
    float4 v = reinterpret_cast<const float4*>(src)[lane];
    float ss = v.x * v.x + v.y * v.y + v.z * v.z + v.w * v.w;
    #pragma unroll
    for (int off = 16; off > 0; off >>= 1)
        ss += __shfl_xor_sync(0xffffffffu, ss, off);
    float inv = 1.0f / fmaxf(sqrtf(ss), 1e-8f);
    float4 o; o.x = v.x * inv; o.y = v.y * inv; o.z = v.z * inv; o.w = v.w * inv;
    reinterpret_cast<float4*>(g_zn + (size_t)row * DIMK)[lane] = o;

    __nv_bfloat162 p0 = __float22bfloat162_rn(make_float2(o.x, o.y));
    __nv_bfloat162 p1 = __float22bfloat162_rn(make_float2(o.z, o.w));
    uint32_t* dst = reinterpret_cast<uint32_t*>(g_zbf + (size_t)row * DIMK);
    dst[lane * 2]     = *reinterpret_cast<uint32_t*>(&p0);
    dst[lane * 2 + 1] = *reinterpret_cast<uint32_t*>(&p1);
}

// ---------------------------------------------------------------------------
// Kernel 2: 128x128x128 bf16 mma.sync tile + fused exp row-sum epilogue
//   smem: sA 32KB | sB 32KB | ssum 1KB
// ---------------------------------------------------------------------------
#define SMEM_SSUM 65536
#define SMEM_TOT  (65536 + 1024)

__global__ __launch_bounds__(256, 2)
void k_mma_tile() {
    extern __shared__ char smem[];
    const uint32_t sa = smem_u32(smem);
    const uint32_t sb = sa + 32768;
    float* ssum = reinterpret_cast<float*>(smem + SMEM_SSUM);

    const int tid  = threadIdx.x;
    const int wid  = tid >> 5;
    const int lane = tid & 31;
    const int bi = blockIdx.y;     // row tile
    const int bj = blockIdx.x;     // col tile

    // cooperative tile load: row-major gmem -> swizzled smem (16B per thread x 8)
    const uint4* gA = reinterpret_cast<const uint4*>(g_zbf + (size_t)bi * 128 * DIMK);
    const uint4* gB = reinterpret_cast<const uint4*>(g_zbf + (size_t)bj * 128 * DIMK);
    #pragma unroll
    for (int i = 0; i < 8; i++) {
        int idx = tid + i * 256;            // 0..2047
        int row = idx >> 4, c = idx & 15;
        uint32_t off = swz(row, c);
        *reinterpret_cast<uint4*>(smem + off)         = gA[idx];
        *reinterpret_cast<uint4*>(smem + 32768 + off) = gB[idx];
    }
    __syncthreads();

    // warp layout: 4 (M) x 2 (N); warp tile 32 x 64
    const int arow0 = (wid & 3) * 32;
    const int bcol0 = (wid >> 2) * 64;
    const int g  = lane >> 3;      // ldmatrix group 0..3
    const int rr = lane & 7;

    float acc[2][8][4];
    #pragma unroll
    for (int mt = 0; mt < 2; mt++)
        #pragma unroll
        for (int nt = 0; nt < 8; nt++)
            #pragma unroll
            for (int q = 0; q < 4; q++) acc[mt][nt][q] = 0.0f;

    #pragma unroll
    for (int ks = 0; ks < 8; ks++) {
        const int kc = ks * 2;     // 16B-chunk base of this k-step (16 bf16)
        uint32_t afr[2][4], bfr[4][4];
        #pragma unroll
        for (int mt = 0; mt < 2; mt++) {
            // matrices: m0 rows0-7/k0, m1 rows8-15/k0, m2 rows0-7/k8, m3 rows8-15/k8
            uint32_t addr = sa + swz(arow0 + mt * 16 + rr + (g & 1) * 8, kc + (g >> 1));
            ldsm_x4(addr, afr[mt]);
        }
        #pragma unroll
        for (int nq = 0; nq < 4; nq++) {
            // matrices: m0 n0-7/k0, m1 n0-7/k8, m2 n8-15/k0, m3 n8-15/k8
            uint32_t addr = sb + swz(bcol0 + nq * 16 + (g >> 1) * 8 + rr, kc + (g & 1));
            ldsm_x4(addr, bfr[nq]);
        }
        #pragma unroll
        for (int mt = 0; mt < 2; mt++)
            #pragma unroll
            for (int nt = 0; nt < 8; nt++)
                mma16816(acc[mt][nt], afr[mt], bfr[nt >> 1][(nt & 1) * 2],
                         bfr[nt >> 1][(nt & 1) * 2 + 1]);
    }

    // epilogue: exp2((cos-1)*2*log2e), mask diagonal, per-row sums
    const float CEXP = 2.8853900817779268f;   // 2 * log2(e)
    #pragma unroll
    for (int mt = 0; mt < 2; mt++) {
        #pragma unroll
        for (int rh = 0; rh < 2; rh++) {
            int lrow = arow0 + mt * 16 + (lane >> 2) + rh * 8;
            int grow = bi * 128 + lrow;
            float rs = 0.0f;
            #pragma unroll
            for (int nt = 0; nt < 8; nt++) {
                #pragma unroll
                for (int c = 0; c < 2; c++) {
                    float s = acc[mt][nt][rh * 2 + c];
                    int gcol = bj * 128 + bcol0 + nt * 8 + (lane & 3) * 2 + c;
                    float e = ex2_approx((s - 1.0f) * CEXP);
                    if (grow == gcol) e = 0.0f;
                    rs += e;
                }
            }
            rs += __shfl_xor_sync(0xffffffffu, rs, 1);
            rs += __shfl_xor_sync(0xffffffffu, rs, 2);
            if ((lane & 3) == 0) ssum[(wid >> 2) * 128 + lrow] = rs;
        }
    }
    __syncthreads();
    if (tid < 128)
        g_part[(size_t)bj * NROWS + bi * 128 + tid] = ssum[tid] + ssum[128 + tid];
}

// ---------------------------------------------------------------------------
// Kernel 3: per-row loss = 2 + ln(sumexp) - 2*cos(i, pos(i)).  Warp per row.
// ---------------------------------------------------------------------------
__global__ __launch_bounds__(256)
void k_rowloss() {
    int warp = threadIdx.x >> 5;
    int lane = threadIdx.x & 31;
    int row  = blockIdx.x * 8 + warp;
    if (row >= NROWS) return;

    int p = (row < BATCH) ? row + BATCH : row - BATCH;
    float4 a = reinterpret_cast<const float4*>(g_zn + (size_t)row * DIMK)[lane];
    float4 b = reinterpret_cast<const float4*>(g_zn + (size_t)p * DIMK)[lane];
    float dot = a.x * b.x + a.y * b.y + a.z * b.z + a.w * b.w;
    #pragma unroll
    for (int off = 16; off > 0; off >>= 1)
        dot += __shfl_xor_sync(0xffffffffu, dot, off);

    float se = g_part[(size_t)lane * NROWS + row] +
               g_part[(size_t)(lane + 32) * NROWS + row];
    #pragma unroll
    for (int off = 16; off > 0; off >>= 1)
        se += __shfl_xor_sync(0xffffffffu, se, off);

    if (lane == 0) {
        float lnse = lg2_approx(se) * 0.6931471805599453f;
        g_rowloss[row] = 2.0f + lnse - 2.0f * dot;
    }
}

// ---------------------------------------------------------------------------
// Kernel 4: deterministic final reduction -> out[0] = sum / N
// ---------------------------------------------------------------------------
__global__ __launch_bounds__(256)
void k_finalreduce(float* __restrict__ out) {
    __shared__ float s[256];
    int tid = threadIdx.x;
    float acc = 0.0f;
    for (int i = tid; i < NROWS; i += 256) acc += g_rowloss[i];
    s[tid] = acc;
    __syncthreads();
    #pragma unroll
    for (int off = 128; off > 0; off >>= 1) {
        if (tid < off) s[tid] += s[tid + off];
        __syncthreads();
    }
    if (tid == 0) out[0] = s[0] / (float)NROWS;
}

// ---------------------------------------------------------------------------
extern "C" void kernel_launch(void* const* d_in, const int* in_sizes, int n_in,
                              void* d_out, int out_size) {
    const float* zx = (const float*)d_in[0];
    const float* zy = (const float*)d_in[1];
    float* out = (float*)d_out;

    cudaFuncSetAttribute(k_mma_tile, cudaFuncAttributeMaxDynamicSharedMemorySize, SMEM_TOT);

    k_normalize<<<NROWS / 8, 256>>>(zx, zy);
    dim3 grid(NTILE, NTILE);            // (bj, bi)
    k_mma_tile<<<grid, 256, SMEM_TOT>>>();
    k_rowloss<<<NROWS / 8, 256>>>();
    k_finalreduce<<<1, 256>>>(out);
}

// round 5
// speedup vs baseline: 11.1046x; 1.4038x over previous
#include <cuda_runtime.h>
#include <cuda_bf16.h>
#include <cstdint>

// Problem constants (fixed shapes for NTXent_678604833492)
#define BATCH 4096
#define NROWS 8192          // 2*BATCH
#define DIMK  128
#define NTILE 64            // NROWS / 128
#define NPAIR 2080          // NTILE*(NTILE+1)/2 upper-triangle tiles

// Scratch (__device__ globals; allocation-free rule)
__device__ float g_zn[NROWS * DIMK];                 // normalized fp32 (4 MB)
__device__ __nv_bfloat16 g_zbf[NROWS * DIMK];        // normalized bf16, row-major (2 MB)
__device__ float g_part[NTILE * NROWS];              // per-coltile row sumexp (2 MB)
__device__ float g_blockloss[NROWS / 8];             // per-block loss partials

// ---------------------------------------------------------------------------
// helpers
// ---------------------------------------------------------------------------
__device__ __forceinline__ float ex2_approx(float x) {
    float r; asm("ex2.approx.ftz.f32 %0, %1;" : "=f"(r) : "f"(x)); return r;
}
__device__ __forceinline__ float lg2_approx(float x) {
    float r; asm("lg2.approx.f32 %0, %1;" : "=f"(r) : "f"(x)); return r;
}
__device__ __forceinline__ uint32_t smem_u32(const void* p) {
    uint32_t a;
    asm("{ .reg .u64 t; cvta.to.shared.u64 t, %1; cvt.u32.u64 %0, t; }" : "=r"(a) : "l"(p));
    return a;
}
__device__ __forceinline__ void ldsm_x4(uint32_t addr, uint32_t* r) {
    asm volatile("ldmatrix.sync.aligned.m8n8.x4.shared.b16 {%0,%1,%2,%3}, [%4];"
                 : "=r"(r[0]), "=r"(r[1]), "=r"(r[2]), "=r"(r[3]) : "r"(addr));
}
__device__ __forceinline__ void mma16816(float* d, const uint32_t* a, uint32_t b0, uint32_t b1) {
    asm volatile(
        "mma.sync.aligned.m16n8k16.row.col.f32.bf16.bf16.f32 "
        "{%0,%1,%2,%3}, {%4,%5,%6,%7}, {%8,%9}, {%0,%1,%2,%3};"
        : "+f"(d[0]), "+f"(d[1]), "+f"(d[2]), "+f"(d[3])
        : "r"(a[0]), "r"(a[1]), "r"(a[2]), "r"(a[3]), "r"(b0), "r"(b1));
}

// smem tile addressing: row-major 128 rows x 256B, 16B chunk XOR-swizzled by row&7
__device__ __forceinline__ uint32_t swz(int row, int kchunk /*16B units*/) {
    return ((uint32_t)row << 8) + (uint32_t)((kchunk ^ (row & 7)) << 4);
}

// ---------------------------------------------------------------------------
// Kernel 1: normalize rows -> g_zn (fp32) and g_zbf (bf16 row-major)
// ---------------------------------------------------------------------------
__global__ __launch_bounds__(256)
void k_normalize(const float* __restrict__ zx, const float* __restrict__ zy) {
    int warp = threadIdx.x >> 5;
    int lane = threadIdx.x & 31;
    int row  = blockIdx.x * 8 + warp;
    if (row >= NROWS) return;

    const float* src = (row < BATCH) ? (zx + (size_t)row * DIMK)
                                     : (zy + (size_t)(row - BATCH) * DIMK);
    float4 v = reinterpret_cast<const float4*>(src)[lane];
    float ss = v.x * v.x + v.y * v.y + v.z * v.z + v.w * v.w;
    #pragma unroll
    for (int off = 16; off > 0; off >>= 1)
        ss += __shfl_xor_sync(0xffffffffu, ss, off);
    float inv = 1.0f / fmaxf(sqrtf(ss), 1e-8f);
    float4 o; o.x = v.x * inv; o.y = v.y * inv; o.z = v.z * inv; o.w = v.w * inv;
    reinterpret_cast<float4*>(g_zn + (size_t)row * DIMK)[lane] = o;

    __nv_bfloat162 p0 = __float22bfloat162_rn(make_float2(o.x, o.y));
    __nv_bfloat162 p1 = __float22bfloat162_rn(make_float2(o.z, o.w));
    uint32_t* dst = reinterpret_cast<uint32_t*>(g_zbf + (size_t)row * DIMK);
    dst[lane * 2]     = *reinterpret_cast<uint32_t*>(&p0);
    dst[lane * 2 + 1] = *reinterpret_cast<uint32_t*>(&p1);
}

// ---------------------------------------------------------------------------
// Kernel 2: symmetric 128x128x128 bf16 mma.sync tile (upper triangle only)
//   off-diag tile (bi<bj): row sums -> g_part[bj][bi-block rows]
//                          col sums -> g_part[bi][bj-block rows]  (symmetry)
//   diag tile: row sums with diagonal masked.
//   smem: sA 32KB | sB 32KB | ssum 1KB | scol 2KB
// ---------------------------------------------------------------------------
#define SMEM_SSUM 65536
#define SMEM_SCOL (65536 + 1024)
#define SMEM_TOT  (65536 + 1024 + 2048)

__global__ __launch_bounds__(256, 2)
void k_mma_tile() {
    extern __shared__ char smem[];
    const uint32_t sa = smem_u32(smem);
    float* ssum = reinterpret_cast<float*>(smem + SMEM_SSUM);   // [2][128]
    float* scol = reinterpret_cast<float*>(smem + SMEM_SCOL);   // [128][4]

    const int tid  = threadIdx.x;
    const int wid  = tid >> 5;
    const int lane = tid & 31;

    // decode upper-triangle pair (bi <= bj) from linear block id
    int t = blockIdx.x, bi = 0;
    while (t >= NTILE - bi) { t -= NTILE - bi; bi++; }
    const int bj = bi + t;
    const bool diag = (bi == bj);

    // cooperative tile load: row-major gmem -> swizzled smem
    const uint4* gA = reinterpret_cast<const uint4*>(g_zbf + (size_t)bi * 128 * DIMK);
    const uint4* gB = reinterpret_cast<const uint4*>(g_zbf + (size_t)bj * 128 * DIMK);
    #pragma unroll
    for (int i = 0; i < 8; i++) {
        int idx = tid + i * 256;            // 0..2047
        int row = idx >> 4, c = idx & 15;
        uint32_t off = swz(row, c);
        *reinterpret_cast<uint4*>(smem + off) = gA[idx];
        if (!diag)
            *reinterpret_cast<uint4*>(smem + 32768 + off) = gB[idx];
    }
    __syncthreads();
    const uint32_t sb = diag ? sa : (sa + 32768);

    // warp layout: 4 (M) x 2 (N); warp tile 32 x 64
    const int mw = wid & 3;
    const int arow0 = mw * 32;
    const int bcol0 = (wid >> 2) * 64;
    const int g  = lane >> 3;
    const int rr = lane & 7;

    float acc[2][8][4];
    #pragma unroll
    for (int mt = 0; mt < 2; mt++)
        #pragma unroll
        for (int nt = 0; nt < 8; nt++)
            #pragma unroll
            for (int q = 0; q < 4; q++) acc[mt][nt][q] = 0.0f;

    #pragma unroll
    for (int ks = 0; ks < 8; ks++) {
        const int kc = ks * 2;
        uint32_t afr[2][4], bfr[4][4];
        #pragma unroll
        for (int mt = 0; mt < 2; mt++) {
            uint32_t addr = sa + swz(arow0 + mt * 16 + rr + (g & 1) * 8, kc + (g >> 1));
            ldsm_x4(addr, afr[mt]);
        }
        #pragma unroll
        for (int nq = 0; nq < 4; nq++) {
            uint32_t addr = sb + swz(bcol0 + nq * 16 + (g >> 1) * 8 + rr, kc + (g & 1));
            ldsm_x4(addr, bfr[nq]);
        }
        #pragma unroll
        for (int mt = 0; mt < 2; mt++)
            #pragma unroll
            for (int nt = 0; nt < 8; nt++)
                mma16816(acc[mt][nt], afr[mt], bfr[nt >> 1][(nt & 1) * 2],
                         bfr[nt >> 1][(nt & 1) * 2 + 1]);
    }

    // epilogue: e = exp2((cos-1)*2*log2e); accumulate row sums and col sums
    const float CEXP = 2.8853900817779268f;   // 2 * log2(e)
    float cs[8][2];
    #pragma unroll
    for (int nt = 0; nt < 8; nt++) { cs[nt][0] = 0.0f; cs[nt][1] = 0.0f; }

    #pragma unroll
    for (int mt = 0; mt < 2; mt++) {
        #pragma unroll
        for (int rh = 0; rh < 2; rh++) {
            int lrow = arow0 + mt * 16 + (lane >> 2) + rh * 8;
            int grow = bi * 128 + lrow;
            float rs = 0.0f;
            #pragma unroll
            for (int nt = 0; nt < 8; nt++) {
                #pragma unroll
                for (int c = 0; c < 2; c++) {
                    float s = acc[mt][nt][rh * 2 + c];
                    float e = ex2_approx((s - 1.0f) * CEXP);
                    if (diag) {
                        int gcol = bj * 128 + bcol0 + nt * 8 + (lane & 3) * 2 + c;
                        if (grow == gcol) e = 0.0f;
                    }
                    rs += e;
                    cs[nt][c] += e;
                }
            }
            rs += __shfl_xor_sync(0xffffffffu, rs, 1);
            rs += __shfl_xor_sync(0xffffffffu, rs, 2);
            if ((lane & 3) == 0) ssum[(wid >> 2) * 128 + lrow] = rs;
        }
    }

    if (!diag) {
        // reduce col partials over the 8 row-threads (strides 4, 8, 16)
        #pragma unroll
        for (int nt = 0; nt < 8; nt++) {
            #pragma unroll
            for (int c = 0; c < 2; c++) {
                float v = cs[nt][c];
                v += __shfl_xor_sync(0xffffffffu, v, 4);
                v += __shfl_xor_sync(0xffffffffu, v, 8);
                v += __shfl_xor_sync(0xffffffffu, v, 16);
                cs[nt][c] = v;
            }
        }
        if ((lane >> 2) == 0) {
            #pragma unroll
            for (int nt = 0; nt < 8; nt++)
                #pragma unroll
                for (int c = 0; c < 2; c++) {
                    int col = bcol0 + nt * 8 + (lane & 3) * 2 + c;
                    scol[col * 4 + mw] = cs[nt][c];
                }
        }
    }
    __syncthreads();

    if (tid < 128) {
        g_part[(size_t)bj * NROWS + bi * 128 + tid] = ssum[tid] + ssum[128 + tid];
        if (!diag) {
            float cv = scol[tid * 4] + scol[tid * 4 + 1]
                     + scol[tid * 4 + 2] + scol[tid * 4 + 3];
            g_part[(size_t)bi * NROWS + bj * 128 + tid] = cv;
        }
    }
}

// ---------------------------------------------------------------------------
// Kernel 3: per-row loss = 2 + ln(sumexp) - 2*cos(i, pos(i)); block-sum of 8
// ---------------------------------------------------------------------------
__global__ __launch_bounds__(256)
void k_rowloss() {
    __shared__ float sl[8];
    int warp = threadIdx.x >> 5;
    int lane = threadIdx.x & 31;
    int row  = blockIdx.x * 8 + warp;

    int p = (row < BATCH) ? row + BATCH : row - BATCH;
    float4 a = reinterpret_cast<const float4*>(g_zn + (size_t)row * DIMK)[lane];
    float4 b = reinterpret_cast<const float4*>(g_zn + (size_t)p * DIMK)[lane];
    float dot = a.x * b.x + a.y * b.y + a.z * b.z + a.w * b.w;
    #pragma unroll
    for (int off = 16; off > 0; off >>= 1)
        dot += __shfl_xor_sync(0xffffffffu, dot, off);

    float se = g_part[(size_t)lane * NROWS + row] +
               g_part[(size_t)(lane + 32) * NROWS + row];
    #pragma unroll
    for (int off = 16; off > 0; off >>= 1)
        se += __shfl_xor_sync(0xffffffffu, se, off);

    if (lane == 0) {
        float lnse = lg2_approx(se) * 0.6931471805599453f;
        sl[warp] = 2.0f + lnse - 2.0f * dot;
    }
    __syncthreads();
    if (threadIdx.x == 0) {
        float s = 0.0f;
        #pragma unroll
        for (int i = 0; i < 8; i++) s += sl[i];
        g_blockloss[blockIdx.x] = s;
    }
}

// ---------------------------------------------------------------------------
// Kernel 4: deterministic final reduction over 1024 block partials
// ---------------------------------------------------------------------------
__global__ __launch_bounds__(256)
void k_finalreduce(float* __restrict__ out) {
    __shared__ float s[256];
    int tid = threadIdx.x;
    float acc = 0.0f;
    #pragma unroll
    for (int i = 0; i < 4; i++) acc += g_blockloss[tid + i * 256];
    s[tid] = acc;
    __syncthreads();
    #pragma unroll
    for (int off = 128; off > 0; off >>= 1) {
        if (tid < off) s[tid] += s[tid + off];
        __syncthreads();
    }
    if (tid == 0) out[0] = s[0] / (float)NROWS;
}

// ---------------------------------------------------------------------------
extern "C" void kernel_launch(void* const* d_in, const int* in_sizes, int n_in,
                              void* d_out, int out_size) {
    const float* zx = (const float*)d_in[0];
    const float* zy = (const float*)d_in[1];
    float* out = (float*)d_out;

    cudaFuncSetAttribute(k_mma_tile, cudaFuncAttributeMaxDynamicSharedMemorySize, SMEM_TOT);

    k_normalize<<<NROWS / 8, 256>>>(zx, zy);
    k_mma_tile<<<NPAIR, 256, SMEM_TOT>>>();
    k_rowloss<<<NROWS / 8, 256>>>();
    k_finalreduce<<<1, 256>>>(out);
}